// round 1
// baseline (speedup 1.0000x reference)
#include <cuda_runtime.h>
#include <math.h>
#include <stdint.h>

#define EXER_N 10000
#define STU_N  20000
#define NTOT   30000
#define DD     128
#define HH     3
#define HD     384
#define CAP    96
#define BATCH  2048

// ---------------- scratch arena (device globals; no cudaMalloc allowed) ----
#define SZF(x) ((size_t)(x))
static constexpr size_t O_fE    = 0;                                   // 3*EXER_N*HD
static constexpr size_t O_elE   = O_fE    + SZF(3)*EXER_N*HD;
static constexpr size_t O_erD   = O_elE   + SZF(3)*EXER_N*3;
static constexpr size_t O_zE    = O_erD   + SZF(EXER_N)*3;
static constexpr size_t O_zlE   = O_zE    + SZF(3)*EXER_N*DD;
static constexpr size_t O_zrD   = O_zlE   + SZF(3)*EXER_N;
static constexpr size_t O_bz    = O_zrD   + SZF(EXER_N);
static constexpr size_t O_fS    = O_bz    + SZF(5)*DD;
static constexpr size_t O_elS   = O_fS    + SZF(STU_N)*HD;
static constexpr size_t O_erS   = O_elS   + SZF(STU_N)*3;
static constexpr size_t O_rst   = O_erS   + SZF(STU_N)*3;
static constexpr size_t O_zS    = O_rst   + SZF(STU_N)*HD;
static constexpr size_t O_zlS   = O_zS    + SZF(STU_N)*DD;
static constexpr size_t O_zrS   = O_zlS   + SZF(STU_N);
static constexpr size_t O_a     = O_zrS   + SZF(STU_N);
static constexpr size_t O_b     = O_a     + SZF(STU_N)*DD;
static constexpr size_t O_c     = O_b     + SZF(STU_N)*DD;
static constexpr size_t O_d     = O_c     + SZF(STU_N)*DD;
static constexpr size_t O_bp    = O_d     + SZF(STU_N)*DD;
static constexpr size_t O_stu1  = O_bp    + SZF(STU_N)*DD;
static constexpr size_t O_stu1p = O_stu1  + SZF(STU_N)*DD;
static constexpr size_t O_A2    = O_stu1p + SZF(STU_N)*DD;
static constexpr size_t O_B2    = O_A2    + SZF(STU_N)*DD;
static constexpr size_t O_stu2  = O_B2    + SZF(STU_N)*DD;
static constexpr size_t O_stu2p = O_stu2  + SZF(STU_N)*DD;
static constexpr size_t O_nb    = O_stu2p + SZF(STU_N)*DD;
static constexpr size_t O_nbp   = O_nb    + SZF(BATCH)*DD;
static constexpr size_t O_S     = O_nbp   + SZF(BATCH)*DD;
static constexpr size_t O_lossd = O_S     + DD;
static constexpr size_t F_TOT   = O_lossd + 4;

static constexpr size_t OI_adj  = 0;                      // 3*STU_N*CAP
static constexpr size_t OI_cnt  = SZF(3)*STU_N*CAP;
static constexpr size_t I_TOT   = OI_cnt + SZF(3)*STU_N;

__device__ __align__(256) float g_farena[F_TOT];
__device__ __align__(256) int   g_iarena[I_TOT];

// ---------------- generic SGEMM: C = A[MxK] @ B[KxN] (+C)(+bias)(+add) -----
// row-major everywhere. N%64==0, K%16==0 required; M arbitrary.
__global__ void sgemm(const float* __restrict__ A, const float* __restrict__ B,
                      float* __restrict__ C, int M, int N, int K,
                      const float* __restrict__ bias,
                      const float* __restrict__ addm,
                      int accumulate)
{
    __shared__ float As[16][64];
    __shared__ float Bs[16][64];
    const int tid = threadIdx.x;                 // 256 threads
    const int bm  = blockIdx.y * 64;
    const int bn  = blockIdx.x * 64;
    const int ty  = tid >> 4;                    // 0..15
    const int tx  = tid & 15;                    // 0..15
    const int la_m = tid >> 2;                   // 0..63
    const int la_k = (tid & 3) * 4;              // 0,4,8,12
    const int lb_k = tid >> 4;                   // 0..15
    const int lb_n = (tid & 15) * 4;             // 0..60

    float acc[4][4];
#pragma unroll
    for (int i = 0; i < 4; i++)
#pragma unroll
        for (int j = 0; j < 4; j++) acc[i][j] = 0.f;

    for (int k0 = 0; k0 < K; k0 += 16) {
        float4 av;
        if (bm + la_m < M) av = *(const float4*)(A + (size_t)(bm + la_m) * K + k0 + la_k);
        else av = make_float4(0.f, 0.f, 0.f, 0.f);
        As[la_k + 0][la_m] = av.x;
        As[la_k + 1][la_m] = av.y;
        As[la_k + 2][la_m] = av.z;
        As[la_k + 3][la_m] = av.w;
        float4 bv = *(const float4*)(B + (size_t)(k0 + lb_k) * N + bn + lb_n);
        *(float4*)(&Bs[lb_k][lb_n]) = bv;
        __syncthreads();
#pragma unroll
        for (int k = 0; k < 16; k++) {
            float am[4], bnv[4];
#pragma unroll
            for (int i = 0; i < 4; i++) am[i]  = As[k][ty * 4 + i];
#pragma unroll
            for (int j = 0; j < 4; j++) bnv[j] = Bs[k][tx * 4 + j];
#pragma unroll
            for (int i = 0; i < 4; i++)
#pragma unroll
                for (int j = 0; j < 4; j++) acc[i][j] += am[i] * bnv[j];
        }
        __syncthreads();
    }
#pragma unroll
    for (int i = 0; i < 4; i++) {
        int m = bm + ty * 4 + i;
        if (m >= M) continue;
#pragma unroll
        for (int j = 0; j < 4; j++) {
            int n = bn + tx * 4 + j;
            float v = acc[i][j];
            if (accumulate) v += C[(size_t)m * N + n];
            if (bias)       v += bias[n];
            if (addm)       v += addm[(size_t)m * N + n];
            C[(size_t)m * N + n] = v;
        }
    }
}

// ---------------- small utility kernels ------------------------------------
__global__ void zero_int(int* p, int n) {
    int i = blockIdx.x * blockDim.x + threadIdx.x;
    if (i < n) p[i] = 0;
}

__global__ void copy_f(const float* __restrict__ s, float* __restrict__ d, int n) {
    int i = blockIdx.x * blockDim.x + threadIdx.x;
    if (i < n) d[i] = s[i];
}

// adjacency buckets by (dst - EXER_N); only stu dst kept
__global__ void build_adj(const int* __restrict__ src, const int* __restrict__ dst,
                          int ecnt, int* __restrict__ adj, int* __restrict__ cnt) {
    int i = blockIdx.x * blockDim.x + threadIdx.x;
    if (i >= ecnt) return;
    int d = dst[i];
    if (d < EXER_N) return;
    int dl = d - EXER_N;
    int slot = atomicAdd(&cnt[dl], 1);
    if (slot < CAP) adj[(size_t)dl * CAP + slot] = src[i];
}

// bz[p] = gat_b[p] @ fc_W[p] + fc_b[p]   (per-layer effective bias, 128-vec)
__global__ void bz_kernel(const float* __restrict__ gb, const float* __restrict__ fcW,
                          const float* __restrict__ fcb, float* __restrict__ bz) {
    int p = blockIdx.x, n = threadIdx.x;   // 5 blocks x 128
    const float* g = gb + (size_t)p * HD;
    const float* W = fcW + (size_t)p * HD * DD;
    float s = fcb[(size_t)p * DD + n];
    for (int k = 0; k < HD; k++) s += g[k] * W[(size_t)k * DD + n];
    bz[(size_t)p * DD + n] = s;
}

// el[n,h]=sum_d f[n,h,d]*al[h,d], er likewise. 1 block/node, 128 threads.
__global__ void el_er_kernel(const float* __restrict__ f, const float* __restrict__ al,
                             const float* __restrict__ ar,
                             float* __restrict__ el, float* __restrict__ er) {
    int n = blockIdx.x, t = threadIdx.x;
    const float* fr = f + (size_t)n * HD;
    float pel[3], per[3];
#pragma unroll
    for (int h = 0; h < 3; h++) {
        float v = fr[h * DD + t];
        pel[h] = v * al[h * DD + t];
        per[h] = v * ar[h * DD + t];
    }
#pragma unroll
    for (int off = 16; off; off >>= 1) {
#pragma unroll
        for (int h = 0; h < 3; h++) {
            pel[h] += __shfl_xor_sync(0xffffffffu, pel[h], off);
            per[h] += __shfl_xor_sync(0xffffffffu, per[h], off);
        }
    }
    __shared__ float red[4][6];
    int w = t >> 5;
    if ((t & 31) == 0) {
#pragma unroll
        for (int h = 0; h < 3; h++) { red[w][h] = pel[h]; red[w][3 + h] = per[h]; }
    }
    __syncthreads();
    if (t < 6) {
        float v = red[0][t] + red[1][t] + red[2][t] + red[3][t];
        if (t < 3) el[(size_t)n * 3 + t] = v;
        else       er[(size_t)n * 3 + (t - 3)] = v;
    }
}

// zl[n]=z[n]·aW[:128], zr[n]=z[n]·aW[128:]
__global__ void zlzr_kernel(const float* __restrict__ z, const float* __restrict__ aW,
                            float* __restrict__ zl, float* __restrict__ zr) {
    int n = blockIdx.x, t = threadIdx.x;
    float v = z[(size_t)n * DD + t];
    float a = v * aW[t];
    float b = v * aW[DD + t];
#pragma unroll
    for (int off = 16; off; off >>= 1) {
        a += __shfl_xor_sync(0xffffffffu, a, off);
        b += __shfl_xor_sync(0xffffffffu, b, off);
    }
    __shared__ float red[4][2];
    int w = t >> 5;
    if ((t & 31) == 0) { red[w][0] = a; red[w][1] = b; }
    __syncthreads();
    if (t < 2) {
        float v2 = red[0][t] + red[1][t] + red[2][t] + red[3][t];
        if (t == 0) zl[n] = v2; else zr[n] = v2;
    }
}

// attention stage 1: softmax over incoming edges (3 heads) + weighted f-sum
__global__ void attn1_kernel(const int* __restrict__ adj, const int* __restrict__ cnt,
                             const float* __restrict__ elE, const float* __restrict__ elS,
                             const float* __restrict__ erS,
                             const float* __restrict__ fE, const float* __restrict__ fS,
                             float* __restrict__ rst) {
    int dl = blockIdx.x, t = threadIdx.x;
    int deg = cnt[dl]; if (deg > CAP) deg = CAP;
    __shared__ int   ssrc[CAP];
    __shared__ float se[CAP * 3];
    __shared__ float sm[3], ssum[3];
    float er0 = erS[(size_t)dl * 3 + 0];
    float er1 = erS[(size_t)dl * 3 + 1];
    float er2 = erS[(size_t)dl * 3 + 2];
    if (t < deg) {
        int s = adj[(size_t)dl * CAP + t];
        ssrc[t] = s;
        const float* el = (s < EXER_N) ? (elE + (size_t)s * 3) : (elS + (size_t)(s - EXER_N) * 3);
        float e0 = el[0] + er0, e1 = el[1] + er1, e2 = el[2] + er2;
        se[t * 3 + 0] = e0 > 0.f ? e0 : 0.2f * e0;
        se[t * 3 + 1] = e1 > 0.f ? e1 : 0.2f * e1;
        se[t * 3 + 2] = e2 > 0.f ? e2 : 0.2f * e2;
    }
    __syncthreads();
    int w = t >> 5, lane = t & 31;
    if (w < 3) {
        float m = -3.0e38f;
        for (int j = lane; j < deg; j += 32) m = fmaxf(m, se[j * 3 + w]);
#pragma unroll
        for (int off = 16; off; off >>= 1) m = fmaxf(m, __shfl_xor_sync(0xffffffffu, m, off));
        float s = 0.f;
        for (int j = lane; j < deg; j += 32) s += expf(se[j * 3 + w] - m);
#pragma unroll
        for (int off = 16; off; off >>= 1) s += __shfl_xor_sync(0xffffffffu, s, off);
        if (lane == 0) { sm[w] = m; ssum[w] = s; }
    }
    __syncthreads();
    if (t < deg) {
#pragma unroll
        for (int h = 0; h < 3; h++)
            se[t * 3 + h] = expf(se[t * 3 + h] - sm[h]) / ssum[h];
    }
    __syncthreads();
    float a0 = 0.f, a1 = 0.f, a2 = 0.f;
    for (int j = 0; j < deg; j++) {
        int s = ssrc[j];
        const float* fr = (s < EXER_N) ? (fE + (size_t)s * HD) : (fS + (size_t)(s - EXER_N) * HD);
        float w0 = se[j * 3 + 0], w1 = se[j * 3 + 1], w2 = se[j * 3 + 2];
        a0 += w0 * fr[t];
        a1 += w1 * fr[DD + t];
        a2 += w2 * fr[2 * DD + t];
    }
    size_t o = (size_t)dl * HD;
    rst[o + t] = a0; rst[o + DD + t] = a1; rst[o + 2 * DD + t] = a2;
}

// attention stage 2: 1-head softmax + weighted z-sum
__global__ void attn2_kernel(const int* __restrict__ adj, const int* __restrict__ cnt,
                             const float* __restrict__ zlE, const float* __restrict__ zlS,
                             const float* __restrict__ zrS,
                             const float* __restrict__ zE, const float* __restrict__ zS,
                             float* __restrict__ out) {
    int dl = blockIdx.x, t = threadIdx.x;
    int deg = cnt[dl]; if (deg > CAP) deg = CAP;
    __shared__ int   ssrc[CAP];
    __shared__ float se[CAP];
    __shared__ float smx, ssm;
    float zr = zrS[dl];
    if (t < deg) {
        int s = adj[(size_t)dl * CAP + t];
        ssrc[t] = s;
        float zl = (s < EXER_N) ? zlE[s] : zlS[s - EXER_N];
        se[t] = zl + zr;     // NOTE: no leaky_relu on second attention
    }
    __syncthreads();
    if (t < 32) {
        float m = -3.0e38f;
        for (int j = t; j < deg; j += 32) m = fmaxf(m, se[j]);
#pragma unroll
        for (int off = 16; off; off >>= 1) m = fmaxf(m, __shfl_xor_sync(0xffffffffu, m, off));
        float s = 0.f;
        for (int j = t; j < deg; j += 32) s += expf(se[j] - m);
#pragma unroll
        for (int off = 16; off; off >>= 1) s += __shfl_xor_sync(0xffffffffu, s, off);
        if (t == 0) { smx = m; ssm = s; }
    }
    __syncthreads();
    if (t < deg) se[t] = expf(se[t] - smx) / ssm;
    __syncthreads();
    float acc = 0.f;
    for (int j = 0; j < deg; j++) {
        int s = ssrc[j];
        const float* zrow = (s < EXER_N) ? (zE + (size_t)s * DD) : (zS + (size_t)(s - EXER_N) * DD);
        acc += se[j] * zrow[t];
    }
    out[(size_t)dl * DD + t] = acc;
}

// SSL pieces --------------------------------------------------------------
__global__ void norm_rows(const float* __restrict__ emb, const int* __restrict__ ids,
                          float* __restrict__ out) {
    int i = blockIdx.x, t = threadIdx.x;    // BATCH blocks x 128
    int r = ids[i];
    float v = emb[(size_t)r * DD + t];
    float sq = v * v;
#pragma unroll
    for (int off = 16; off; off >>= 1) sq += __shfl_xor_sync(0xffffffffu, sq, off);
    __shared__ float w4[4];
    if ((t & 31) == 0) w4[t >> 5] = sq;
    __syncthreads();
    float tot = w4[0] + w4[1] + w4[2] + w4[3];
    float nrm = sqrtf(tot);
    out[(size_t)i * DD + t] = v / fmaxf(nrm, 1e-12f);
}

__global__ void colsum(const float* __restrict__ nbp, float* __restrict__ S) {
    int t = threadIdx.x;   // 1 block x 128
    float s = 0.f;
    for (int i = 0; i < BATCH; i++) s += nbp[(size_t)i * DD + t];
    S[t] = s;
}

__global__ void loss_kernel(const float* __restrict__ nb, const float* __restrict__ nbp,
                            const float* __restrict__ S, float* __restrict__ out) {
    int t = threadIdx.x;   // 1 block x 256
    float lsum = 0.f;
    for (int i = t; i < BATCH; i += 256) {
        const float* x = nb  + (size_t)i * DD;
        const float* y = nbp + (size_t)i * DD;
        float dg = 0.f, rs = 0.f;
        for (int d = 0; d < DD; d++) {
            float xv = x[d];
            dg += xv * y[d];
            rs += xv * S[d];
        }
        float diag   = dg * 5.0f;            // /0.2
        float rowsum = rs * 5.0f;
        float divided = expf(diag) / (rowsum + 1e-8f);
        float v = fmaxf(divided, 1e-8f);
        lsum += -logf(v);
    }
    __shared__ float red[256];
    red[t] = lsum;
    __syncthreads();
    for (int s = 128; s; s >>= 1) { if (t < s) red[t] += red[t + s]; __syncthreads(); }
    if (t == 0) out[0] = red[0];
}

// ---------------- host orchestration ---------------------------------------
extern "C" void kernel_launch(void* const* d_in, const int* in_sizes, int n_in,
                              void* d_out_, int out_size)
{
    const float* stu_table  = (const float*)d_in[0];
    const float* exer_table = (const float*)d_in[1];
    const float* gat_W  = (const float*)d_in[2];
    const float* attn_l = (const float*)d_in[3];
    const float* attn_r = (const float*)d_in[4];
    const float* gat_b  = (const float*)d_in[5];
    const float* fc_W   = (const float*)d_in[6];
    const float* fc_b   = (const float*)d_in[7];
    const float* aW     = (const float*)d_in[8];
    const float* f1W    = (const float*)d_in[9];
    const float* f1b    = (const float*)d_in[10];
    const float* f2W    = (const float*)d_in[11];
    const float* f2b    = (const float*)d_in[12];
    const int* e_src[3] = {(const int*)d_in[13], (const int*)d_in[15], (const int*)d_in[21]};
    const int* e_dst[3] = {(const int*)d_in[14], (const int*)d_in[16], (const int*)d_in[22]};
    int e_n[3] = {in_sizes[13], in_sizes[15], in_sizes[21]};
    const int* stu_id = (const int*)d_in[23];
    float* d_out = (float*)d_out_;
    (void)n_in;

    float* FA = nullptr; int* IA = nullptr;
    cudaGetSymbolAddress((void**)&FA, g_farena);
    cudaGetSymbolAddress((void**)&IA, g_iarena);

    float* fE    = FA + O_fE;
    float* elE   = FA + O_elE;
    float* erD   = FA + O_erD;
    float* zE    = FA + O_zE;
    float* zlE   = FA + O_zlE;
    float* zrD   = FA + O_zrD;
    float* bz    = FA + O_bz;
    float* fS    = FA + O_fS;
    float* elS   = FA + O_elS;
    float* erS   = FA + O_erS;
    float* rst   = FA + O_rst;
    float* zS    = FA + O_zS;
    float* zlS   = FA + O_zlS;
    float* zrS   = FA + O_zrS;
    float* abuf  = FA + O_a;
    float* bbuf  = FA + O_b;
    float* cbuf  = FA + O_c;
    float* dbuf  = FA + O_d;
    float* bpbuf = FA + O_bp;
    float* stu1  = FA + O_stu1;
    float* stu1p = FA + O_stu1p;
    float* A2    = FA + O_A2;
    float* B2    = FA + O_B2;
    float* stu2  = FA + O_stu2;
    float* stu2p = FA + O_stu2p;
    float* nb    = FA + O_nb;
    float* nbp   = FA + O_nbp;
    float* Sv    = FA + O_S;
    float* lossD = FA + O_lossd;

    const int pidx[3] = {0, 1, 4};   // param slots for edge-bearing layers

    // effective biases (per layer): bz = gat_b @ fc_W + fc_b
    bz_kernel<<<5, 128>>>(gat_b, fc_W, fc_b, bz);

    const int gM_E = (EXER_N + 63) / 64;
    const int gM_S = (STU_N + 63) / 64;

    // ---- per-slot: adjacency + exer-side invariants ----
    for (int s = 0; s < 3; s++) {
        int p = pidx[s];
        int* adj = IA + OI_adj + (size_t)s * STU_N * CAP;
        int* cnt = IA + OI_cnt + (size_t)s * STU_N;
        zero_int<<<(STU_N + 255) / 256, 256>>>(cnt, STU_N);
        build_adj<<<(e_n[s] + 255) / 256, 256>>>(e_src[s], e_dst[s], e_n[s], adj, cnt);

        float* fEs  = fE  + (size_t)s * EXER_N * HD;
        float* zEs  = zE  + (size_t)s * EXER_N * DD;
        float* elEs = elE + (size_t)s * EXER_N * 3;
        float* zlEs = zlE + (size_t)s * EXER_N;

        sgemm<<<dim3(HD / 64, gM_E), 256>>>(exer_table, gat_W + (size_t)p * DD * HD,
                                            fEs, EXER_N, HD, DD, nullptr, nullptr, 0);
        el_er_kernel<<<EXER_N, 128>>>(fEs, attn_l + (size_t)p * HD, attn_r + (size_t)p * HD,
                                      elEs, erD);
        sgemm<<<dim3(DD / 64, gM_E), 256>>>(fEs, fc_W + (size_t)p * HD * DD,
                                            zEs, EXER_N, DD, HD, bz + (size_t)p * DD, nullptr, 0);
        zlzr_kernel<<<EXER_N, 128>>>(zEs, aW + (size_t)p * 2 * DD, zlEs, zrD);
    }

    // ---- layers 2,3 at stu rows: pure per-node transform (self-loop only) ----
    for (int p = 2; p <= 3; p++) {
        float* outp = (p == 2) ? cbuf : dbuf;
        sgemm<<<dim3(HD / 64, gM_S), 256>>>(stu_table, gat_W + (size_t)p * DD * HD,
                                            fS, STU_N, HD, DD, nullptr, nullptr, 0);
        sgemm<<<dim3(DD / 64, gM_S), 256>>>(fS, fc_W + (size_t)p * HD * DD,
                                            outp, STU_N, DD, HD, bz + (size_t)p * DD, nullptr, 0);
    }

    // ---- one GAT invocation (stu rows only) ----
    auto run_gat = [&](int s, const float* xS, float* outb) {
        int p = pidx[s];
        const int* adj = IA + OI_adj + (size_t)s * STU_N * CAP;
        const int* cnt = IA + OI_cnt + (size_t)s * STU_N;
        const float* fEs  = fE  + (size_t)s * EXER_N * HD;
        const float* zEs  = zE  + (size_t)s * EXER_N * DD;
        const float* elEs = elE + (size_t)s * EXER_N * 3;
        const float* zlEs = zlE + (size_t)s * EXER_N;

        sgemm<<<dim3(HD / 64, gM_S), 256>>>(xS, gat_W + (size_t)p * DD * HD,
                                            fS, STU_N, HD, DD, nullptr, nullptr, 0);
        el_er_kernel<<<STU_N, 128>>>(fS, attn_l + (size_t)p * HD, attn_r + (size_t)p * HD,
                                     elS, erS);
        attn1_kernel<<<STU_N, 128>>>(adj, cnt, elEs, elS, erS, fEs, fS, rst);
        sgemm<<<dim3(DD / 64, gM_S), 256>>>(rst, fc_W + (size_t)p * HD * DD,
                                            zS, STU_N, DD, HD, bz + (size_t)p * DD, nullptr, 0);
        zlzr_kernel<<<STU_N, 128>>>(zS, aW + (size_t)p * 2 * DD, zlS, zrS);
        attn2_kernel<<<STU_N, 128>>>(adj, cnt, zlEs, zlS, zrS, zEs, zS, outb);
    };

    // first round on base tables
    run_gat(0, stu_table, abuf);
    run_gat(1, stu_table, bbuf);
    run_gat(2, stu_table, bpbuf);

    // fusion1: stu1 = stu_table + [a|b|c|d]@f1W + f1b  (and stu1p with bp)
    auto fuse1 = [&](const float* bsel, float* dst) {
        sgemm<<<dim3(DD / 64, gM_S), 256>>>(abuf, f1W,              dst, STU_N, DD, DD, nullptr, nullptr, 0);
        sgemm<<<dim3(DD / 64, gM_S), 256>>>(bsel, f1W + 128 * 128,  dst, STU_N, DD, DD, nullptr, nullptr, 1);
        sgemm<<<dim3(DD / 64, gM_S), 256>>>(cbuf, f1W + 256 * 128,  dst, STU_N, DD, DD, nullptr, nullptr, 1);
        sgemm<<<dim3(DD / 64, gM_S), 256>>>(dbuf, f1W + 384 * 128,  dst, STU_N, DD, DD, f1b, stu_table, 1);
    };
    fuse1(bbuf, stu1);
    fuse1(bpbuf, stu1p);

    // expr2(stu1) -> stu2
    run_gat(0, stu1, A2);
    run_gat(1, stu1, B2);
    sgemm<<<dim3(DD / 64, gM_S), 256>>>(A2, f2W,             stu2, STU_N, DD, DD, nullptr, nullptr, 0);
    sgemm<<<dim3(DD / 64, gM_S), 256>>>(B2, f2W + 128 * 128, stu2, STU_N, DD, DD, f2b, stu1, 1);

    // expr2(stu1p) -> stu2p
    run_gat(0, stu1p, A2);
    run_gat(1, stu1p, B2);
    sgemm<<<dim3(DD / 64, gM_S), 256>>>(A2, f2W,             stu2p, STU_N, DD, DD, nullptr, nullptr, 0);
    sgemm<<<dim3(DD / 64, gM_S), 256>>>(B2, f2W + 128 * 128, stu2p, STU_N, DD, DD, f2b, stu1p, 1);

    // ---- outputs ----
    const int NOUT = STU_N * DD;
    if (out_size >= NOUT)
        copy_f<<<(NOUT + 255) / 256, 256>>>(stu2, d_out, NOUT);

    float* lossdst = lossD;
    if (out_size == 1) lossdst = d_out;
    else if (out_size > NOUT) lossdst = d_out + (out_size - 1);

    norm_rows<<<BATCH, 128>>>(stu2,  stu_id, nb);
    norm_rows<<<BATCH, 128>>>(stu2p, stu_id, nbp);
    colsum<<<1, 128>>>(nbp, Sv);
    loss_kernel<<<1, 256>>>(nb, nbp, Sv, lossdst);
}